// round 13
// baseline (speedup 1.0000x reference)
#include <cuda_runtime.h>
#include <cuda_fp16.h>
#include <cstdint>

#define Bb 2
#define Ss 2048
#define Dd 1024
#define Hh 16
#define DKk 64
#define Mm (Bb*Ss)
#define NTILE (Ss/64)

// Scratch (allocation-free rule: __device__ globals). fp16 internal datapath.
__device__ __half g_Xh[(size_t)3*Mm*Dd];       // converted q,k,v inputs
__device__ __half g_Wh[(size_t)4*Dd*Dd];       // converted wq,wk,wv,wo
__device__ __half g_Qh[(size_t)Bb*Hh*Ss*DKk];  // holds Qh * 0.125 * log2(e)
__device__ __half g_Kh[(size_t)Bb*Hh*Ss*DKk];
__device__ __half g_Vh[(size_t)Bb*Hh*Ss*DKk];
__device__ __half g_ctx[(size_t)Bb*Ss*Dd];

// ---------------- PTX helpers ----------------
__device__ __forceinline__ uint32_t sptr(const void* p){
    return (uint32_t)__cvta_generic_to_shared(p);
}
__device__ __forceinline__ void cpa16(uint32_t s, const void* g){
    asm volatile("cp.async.ca.shared.global [%0], [%1], 16;\n" :: "r"(s), "l"(g));
}
__device__ __forceinline__ void cpa4(uint32_t s, const void* g){
    asm volatile("cp.async.ca.shared.global [%0], [%1], 4;\n" :: "r"(s), "l"(g));
}
__device__ __forceinline__ void cp_commit(){ asm volatile("cp.async.commit_group;\n"); }
template<int N> __device__ __forceinline__ void cp_wait(){
    asm volatile("cp.async.wait_group %0;\n" :: "n"(N));
}

__device__ __forceinline__ void ldsm4(uint32_t a, uint32_t* r){
    asm volatile("ldmatrix.sync.aligned.m8n8.x4.shared.b16 {%0,%1,%2,%3},[%4];\n"
        : "=r"(r[0]), "=r"(r[1]), "=r"(r[2]), "=r"(r[3]) : "r"(a));
}
__device__ __forceinline__ void ldsm4t(uint32_t a, uint32_t* r){
    asm volatile("ldmatrix.sync.aligned.m8n8.x4.trans.shared.b16 {%0,%1,%2,%3},[%4];\n"
        : "=r"(r[0]), "=r"(r[1]), "=r"(r[2]), "=r"(r[3]) : "r"(a));
}

__device__ __forceinline__ void mma16(float* c,
    uint32_t a0, uint32_t a1, uint32_t a2, uint32_t a3, uint32_t b0, uint32_t b1)
{
    asm volatile(
      "mma.sync.aligned.m16n8k16.row.col.f32.f16.f16.f32 "
      "{%0,%1,%2,%3},{%4,%5,%6,%7},{%8,%9},{%0,%1,%2,%3};\n"
      : "+f"(c[0]), "+f"(c[1]), "+f"(c[2]), "+f"(c[3])
      : "r"(a0), "r"(a1), "r"(a2), "r"(a3), "r"(b0), "r"(b1));
}

__device__ __forceinline__ void sth2(__half* p, float lo, float hi){
    *(__half2*)p = __floats2half2_rn(lo, hi);
}
__device__ __forceinline__ uint32_t packh2(float lo, float hi){
    __half2 h = __floats2half2_rn(lo, hi);
    return *(uint32_t*)&h;
}
__device__ __forceinline__ float ex2(float x){
    float y; asm("ex2.approx.ftz.f32 %0, %1;" : "=f"(y) : "f"(x)); return y;
}

// head-layout index: m=(b*S+s), n=(h*64+dk) -> [b][h][s][dk]
__device__ __forceinline__ size_t hidx(int m, int n){
    int b = m >> 11;
    int s = m & 2047;
    int h = n >> 6;
    int dk = n & 63;
    return (((size_t)b*Hh + h)*Ss + s)*DKk + dk;
}

// ---------------------------------------------------------------------------
// Convert q,k,v and 4 weights fp32 -> fp16. One thread per float4.
// ---------------------------------------------------------------------------
__global__ void __launch_bounds__(256)
convert_all(const float* __restrict__ q, const float* __restrict__ k,
            const float* __restrict__ v,
            const float* __restrict__ wq, const float* __restrict__ wk,
            const float* __restrict__ wv, const float* __restrict__ wo)
{
    size_t t = (size_t)blockIdx.x*256 + threadIdx.x;
    const float* src; __half* dst; size_t off;
    if (t < ((size_t)3<<20)) {
        int which = (int)(t >> 20);
        off = t & 0xFFFFFu;
        src = (which == 0) ? q : (which == 1) ? k : v;
        dst = g_Xh + ((size_t)which << 22);
    } else {
        size_t t2 = t - ((size_t)3<<20);
        int which = (int)(t2 >> 18);
        off = t2 & 0x3FFFFu;
        src = (which == 0) ? wq : (which == 1) ? wk : (which == 2) ? wv : wo;
        dst = g_Wh + ((size_t)which << 20);
    }
    float4 vv = ((const float4*)src)[off];
    __half2 h0 = __floats2half2_rn(vv.x, vv.y);
    __half2 h1 = __floats2half2_rn(vv.z, vv.w);
    uint2 u; u.x = *(uint32_t*)&h0; u.y = *(uint32_t*)&h1;
    ((uint2*)dst)[off] = u;
}

// ---------------------------------------------------------------------------
// All-half projection GEMM: C[4096,1024] = X @ W^T + bias.
// BK=64 k-tiles, 3-stage cp.async ring, ONE __syncthreads per tile.
// Block 128x128, 8 warps (2m x 4n), warp 64x32.
// ---------------------------------------------------------------------------
#define GST2 72                      // halves per smem row (144B)
#define GSTAGE (128*GST2)            // halves per operand stage
#define GKT2 (Dd/64)                 // 16 k-tiles
#define GEMM_SMEM (3*2*GSTAGE*2)     // bytes = 110592

template<bool HEADOUT>
__device__ __forceinline__ void gemm_body(const __half* __restrict__ X,
                                          const __half* __restrict__ W,
                                          const float* __restrict__ bias,
                                          void* __restrict__ opv,
                                          float oscale)
{
    extern __shared__ __half gsm[];
    __half* As = gsm;                 // [3][GSTAGE]
    __half* Bs = gsm + 3*GSTAGE;      // [3][GSTAGE]

    const int tid = threadIdx.x;
    const int lane = tid & 31, w = tid >> 5;
    const int wm = w >> 2, wn = w & 3;
    const int g = lane >> 2, tg = lane & 3;
    const int by = blockIdx.y, bx = blockIdx.x;

    const int a_off_r = (lane & 7) + ((lane >> 3) & 1) * 8;
    const int a_off_c = (lane >> 4) << 3;
    const int b_off_r = (lane & 7) + ((lane >> 4) << 3);
    const int b_off_c = ((lane >> 3) & 1) << 3;

    const __half* xblk = X + (size_t)(by*128) * Dd;
    const __half* wblk = W + (size_t)(bx*128) * Dd;

    float acc[4][4][4];
    #pragma unroll
    for (int mt = 0; mt < 4; mt++)
        #pragma unroll
        for (int nt = 0; nt < 4; nt++)
            #pragma unroll
            for (int j = 0; j < 4; j++) acc[mt][nt][j] = 0.f;

    auto load_stage = [&](int kt, int st){
        const __half* xs = xblk + kt*64;
        const __half* ws = wblk + kt*64;
        __half* Ast = As + st*GSTAGE;
        __half* Bst = Bs + st*GSTAGE;
        #pragma unroll
        for (int i = 0; i < 4; i++) {
            int id = tid + 256*i;
            int r = id >> 3, c = (id & 7)*8;
            cpa16(sptr(&Ast[r*GST2 + c]), xs + (size_t)r*Dd + c);
            cpa16(sptr(&Bst[r*GST2 + c]), ws + (size_t)r*Dd + c);
        }
    };

    load_stage(0, 0); cp_commit();
    load_stage(1, 1); cp_commit();

    int st = 0;
    for (int kt = 0; kt < GKT2; kt++){
        if (kt == GKT2 - 1) cp_wait<0>(); else cp_wait<1>();
        __syncthreads();
        if (kt + 2 < GKT2) { load_stage(kt + 2, (st + 2) % 3); cp_commit(); }

        const __half* Ast = As + st*GSTAGE;
        const __half* Bst = Bs + st*GSTAGE;
        #pragma unroll
        for (int ks = 0; ks < 64; ks += 16) {
            uint32_t aF[4][4], bF[2][4];
            #pragma unroll
            for (int mt = 0; mt < 4; mt++)
                ldsm4(sptr(&Ast[(wm*64 + mt*16 + a_off_r)*GST2 + ks + a_off_c]), aF[mt]);
            #pragma unroll
            for (int ntp = 0; ntp < 2; ntp++)
                ldsm4(sptr(&Bst[(wn*32 + ntp*16 + b_off_r)*GST2 + ks + b_off_c]), bF[ntp]);
            #pragma unroll
            for (int mt = 0; mt < 4; mt++)
                #pragma unroll
                for (int nt = 0; nt < 4; nt++)
                    mma16(acc[mt][nt], aF[mt][0], aF[mt][1], aF[mt][2], aF[mt][3],
                          bF[nt>>1][(nt&1)*2], bF[nt>>1][(nt&1)*2 + 1]);
        }
        st = (st + 1) % 3;
    }

    #pragma unroll
    for (int mt = 0; mt < 4; mt++) {
        int m0 = by*128 + wm*64 + mt*16 + g;
        #pragma unroll
        for (int nt = 0; nt < 4; nt++) {
            int n0 = bx*128 + wn*32 + nt*8 + tg*2;
            float bv0 = bias[n0], bv1 = bias[n0 + 1];
            if (HEADOUT) {
                __half* op = (__half*)opv;
                sth2(&op[hidx(m0,     n0)], (acc[mt][nt][0] + bv0) * oscale,
                                            (acc[mt][nt][1] + bv1) * oscale);
                sth2(&op[hidx(m0 + 8, n0)], (acc[mt][nt][2] + bv0) * oscale,
                                            (acc[mt][nt][3] + bv1) * oscale);
            } else {
                float* op = (float*)opv;
                *(float2*)&op[(size_t)m0*Dd + n0] =
                    make_float2(acc[mt][nt][0] + bv0, acc[mt][nt][1] + bv1);
                *(float2*)&op[(size_t)(m0+8)*Dd + n0] =
                    make_float2(acc[mt][nt][2] + bv0, acc[mt][nt][3] + bv1);
            }
        }
    }
}

__global__ void __launch_bounds__(256, 2)
gemm_qkv(const float* __restrict__ bq, const float* __restrict__ bk,
         const float* __restrict__ bv)
{
    int mode = blockIdx.z;
    const __half* X = g_Xh + ((size_t)mode << 22);
    const __half* W = g_Wh + ((size_t)mode << 20);
    const float* B = (mode == 0) ? bq : (mode == 1) ? bk : bv;
    __half* op = (mode == 0) ? g_Qh : (mode == 1) ? g_Kh : g_Vh;
    float sc = (mode == 0) ? 0.125f * 1.4426950408889634f : 1.0f;
    gemm_body<true>(X, W, B, op, sc);
}

__global__ void __launch_bounds__(256, 2)
gemm_o(const float* __restrict__ bias, float* __restrict__ outp)
{
    gemm_body<false>(g_ctx, g_Wh + ((size_t)3 << 20), bias, outp, 1.0f);
}

// ---------------------------------------------------------------------------
// Attention (merged). q-tile = 128 rows, 8 warps, warp = 16 q-rows x 64 cols.
// 4-stage cp.async ring for K (pass 1) and K+V (pass 2), one barrier per tile.
// Q fragments hoisted once; fil stays in registers; P in registers between
// score mma and AV mma.
// ---------------------------------------------------------------------------
#define HST 72
#define BQ 128
#define ATTN_SMEM (BQ*HST*2 + 4*64*HST*2*2 + 4*64*4)

__global__ void __launch_bounds__(256, 2)
attn_kernel(const int* __restrict__ mask, float* __restrict__ att)
{
    extern __shared__ __half smh[];
    __half* Qs = smh;                        // 128*HST
    __half* Ks = Qs + BQ*HST;                // 4 x 64*HST
    __half* Vs = Ks + 4*64*HST;              // 4 x 64*HST
    int*  maskv = (int*)(Vs + 4*64*HST);     // 4 x 64

    const int tid = threadIdx.x;
    const int lane = tid & 31, w = tid >> 5;     // warp owns rows w*16..w*16+15
    const int g = lane >> 2, tg = lane & 3;
    const int qb = blockIdx.x, bh = blockIdx.y;
    const int b = bh >> 4, hd = bh & 15;

    const int a_off_r = (lane & 7) + ((lane >> 3) & 1) * 8;
    const int a_off_c = (lane >> 4) << 3;
    const int b_off_r = (lane & 7) + ((lane >> 4) << 3);
    const int b_off_c = ((lane >> 3) & 1) << 3;
    const int v_off_r = (lane & 7) + (((lane >> 3) & 1) << 3);
    const int v_off_c = (lane >> 4) << 3;

    const __half* Qg = g_Qh + ((size_t)bh*Ss + qb*BQ) * DKk;
    const __half* Kg = g_Kh + (size_t)bh*Ss*DKk;
    const __half* Vg = g_Vh + (size_t)bh*Ss*DKk;
    const int*    mg = mask + b*Ss;

    auto load_k = [&](int kt, int st){
        const __half* src = Kg + (size_t)kt*64*64;
        __half* Kst = Ks + st*64*HST;
        #pragma unroll
        for (int i = 0; i < 2; i++) {
            int id = tid + 256*i, r = id >> 3, c = (id & 7)*8;
            cpa16(sptr(&Kst[r*HST + c]), src + r*64 + c);
        }
        if (tid < 64) cpa4(sptr(&maskv[st*64 + tid]), mg + kt*64 + tid);
    };
    auto load_kv = [&](int kt, int st){
        const __half* ksrc = Kg + (size_t)kt*64*64;
        const __half* vsrc = Vg + (size_t)kt*64*64;
        __half* Kst = Ks + st*64*HST;
        __half* Vst = Vs + st*64*HST;
        #pragma unroll
        for (int i = 0; i < 2; i++) {
            int id = tid + 256*i, r = id >> 3, c = (id & 7)*8;
            cpa16(sptr(&Kst[r*HST + c]), ksrc + r*64 + c);
            cpa16(sptr(&Vst[r*HST + c]), vsrc + r*64 + c);
        }
        if (tid < 64) cpa4(sptr(&maskv[st*64 + tid]), mg + kt*64 + tid);
    };

    // prologue: Q + K0 | K1 | K2
    #pragma unroll
    for (int i = 0; i < 4; i++) {
        int id = tid + 256*i, r = id >> 3, c = (id & 7)*8;
        cpa16(sptr(&Qs[r*HST + c]), Qg + r*64 + c);
    }
    load_k(0, 0); cp_commit();
    load_k(1, 1); cp_commit();
    load_k(2, 2); cp_commit();

    cp_wait<2>();
    __syncthreads();

    // Q fragments once (16 rows x 64 cols per warp)
    uint32_t qF[4][4];
    #pragma unroll
    for (int ksi = 0; ksi < 4; ksi++)
        ldsm4(sptr(&Qs[(w*16 + a_off_r)*HST + ksi*16 + a_off_c]), qF[ksi]);

    // ----------------- Pass 1: row sumexp -----------------
    float lp[2] = {0.f, 0.f};

    for (int kt = 0; kt < NTILE; kt++) {
        if (kt) { cp_wait<2>(); __syncthreads(); }
        if (kt + 3 < NTILE) load_k(kt + 3, (kt + 3) & 3);
        cp_commit();

        const __half* Ksb = Ks + (kt & 3)*64*HST;
        const int* mk = maskv + (kt & 3)*64;

        float sa[8][4];
        #pragma unroll
        for (int nt = 0; nt < 8; nt++)
            #pragma unroll
            for (int j = 0; j < 4; j++) sa[nt][j] = 0.f;

        #pragma unroll
        for (int ksi = 0; ksi < 4; ksi++) {
            uint32_t bF[4][4];
            #pragma unroll
            for (int np = 0; np < 4; np++)
                ldsm4(sptr(&Ksb[(np*16 + b_off_r)*HST + ksi*16 + b_off_c]), bF[np]);
            #pragma unroll
            for (int nt = 0; nt < 8; nt++)
                mma16(sa[nt], qF[ksi][0], qF[ksi][1], qF[ksi][2], qF[ksi][3],
                      bF[nt>>1][(nt&1)*2], bF[nt>>1][(nt&1)*2 + 1]);
        }

        #pragma unroll
        for (int nt = 0; nt < 8; nt++) {
            int c0 = nt*8 + 2*tg;
            int m0 = mk[c0], m1 = mk[c0 + 1];
            float s0 = m0 ? sa[nt][0] : -1e9f;
            float s1 = m1 ? sa[nt][1] : -1e9f;
            float s2 = m0 ? sa[nt][2] : -1e9f;
            float s3 = m1 ? sa[nt][3] : -1e9f;
            lp[0] += ex2(s0) + ex2(s1);
            lp[1] += ex2(s2) + ex2(s3);
        }
    }

    // per-warp reduction over tg lanes (warp owns full rows)
    float fil[2];
    #pragma unroll
    for (int e = 0; e < 2; e++) {
        float l = lp[e];
        l += __shfl_xor_sync(0xffffffffu, l, 1);
        l += __shfl_xor_sync(0xffffffffu, l, 2);
        fil[e] = 1.0f / l;
    }

    // pass-2 prologue (slots 0..2 are free: last used at kt 28..30, and the
    // kt=31 barrier proved block-wide completion of those tiles)
    load_kv(0, 0); cp_commit();
    load_kv(1, 1); cp_commit();
    load_kv(2, 2); cp_commit();

    cp_wait<2>();
    __syncthreads();

    // ----------------- Pass 2: attention write + A@V -----------------
    float av[8][4];
    #pragma unroll
    for (int nt = 0; nt < 8; nt++)
        #pragma unroll
        for (int j = 0; j < 4; j++) av[nt][j] = 0.f;

    const int row0 = qb*BQ + w*16 + g;
    float* attr0 = att ? att + ((size_t)bh*Ss + row0)*Ss : nullptr;
    float* attr1 = att ? attr0 + 8*Ss : nullptr;

    for (int kt = 0; kt < NTILE; kt++) {
        if (kt) { cp_wait<2>(); __syncthreads(); }
        if (kt + 3 < NTILE) load_kv(kt + 3, (kt + 3) & 3);
        cp_commit();

        const __half* Ksb = Ks + (kt & 3)*64*HST;
        const __half* Vsb = Vs + (kt & 3)*64*HST;
        const int* mk = maskv + (kt & 3)*64;

        float sa[8][4];
        #pragma unroll
        for (int nt = 0; nt < 8; nt++)
            #pragma unroll
            for (int j = 0; j < 4; j++) sa[nt][j] = 0.f;

        #pragma unroll
        for (int ksi = 0; ksi < 4; ksi++) {
            uint32_t bF[4][4];
            #pragma unroll
            for (int np = 0; np < 4; np++)
                ldsm4(sptr(&Ksb[(np*16 + b_off_r)*HST + ksi*16 + b_off_c]), bF[np]);
            #pragma unroll
            for (int nt = 0; nt < 8; nt++)
                mma16(sa[nt], qF[ksi][0], qF[ksi][1], qF[ksi][2], qF[ksi][3],
                      bF[nt>>1][(nt&1)*2], bF[nt>>1][(nt&1)*2 + 1]);
        }

        // softmax values; fp32 attention writes
        #pragma unroll
        for (int nt = 0; nt < 8; nt++) {
            int c0 = nt*8 + 2*tg;
            int m0 = mk[c0], m1 = mk[c0 + 1];
            float p0 = m0 ? ex2(sa[nt][0]) * fil[0] : 0.f;
            float p1 = m1 ? ex2(sa[nt][1]) * fil[0] : 0.f;
            float p2 = m0 ? ex2(sa[nt][2]) * fil[1] : 0.f;
            float p3 = m1 ? ex2(sa[nt][3]) * fil[1] : 0.f;
            if (att) {
                *(float2*)&attr0[kt*64 + c0] = make_float2(p0, p1);
                *(float2*)&attr1[kt*64 + c0] = make_float2(p2, p3);
            }
            sa[nt][0] = p0; sa[nt][1] = p1; sa[nt][2] = p2; sa[nt][3] = p3;
        }

        // AV: A-frags from registers, B-frags via ldmatrix.trans on V
        #pragma unroll
        for (int ksi = 0; ksi < 4; ksi++) {
            uint32_t ap0 = packh2(sa[2*ksi][0],   sa[2*ksi][1]);
            uint32_t ap1 = packh2(sa[2*ksi][2],   sa[2*ksi][3]);
            uint32_t ap2 = packh2(sa[2*ksi+1][0], sa[2*ksi+1][1]);
            uint32_t ap3 = packh2(sa[2*ksi+1][2], sa[2*ksi+1][3]);
            uint32_t bV[4][4];
            #pragma unroll
            for (int np = 0; np < 4; np++)
                ldsm4t(sptr(&Vsb[(ksi*16 + v_off_r)*HST + np*16 + v_off_c]), bV[np]);
            #pragma unroll
            for (int nt = 0; nt < 8; nt++)
                mma16(av[nt], ap0, ap1, ap2, ap3,
                      bV[nt>>1][(nt&1)*2], bV[nt>>1][(nt&1)*2 + 1]);
        }
    }

    // ctx epilogue: ctx[b][s][h*64+dk] as half
    #pragma unroll
    for (int nt = 0; nt < 8; nt++) {
        int dk = nt*8 + 2*tg;
        size_t i0 = ((size_t)b*Ss + row0)*Dd + hd*DKk + dk;
        sth2(&g_ctx[i0],        av[nt][0], av[nt][1]);
        sth2(&g_ctx[i0 + 8*Dd], av[nt][2], av[nt][3]);
    }
}

// ---------------------------------------------------------------------------

extern "C" void kernel_launch(void* const* d_in, const int* in_sizes, int n_in,
                              void* d_out, int out_size)
{
    const float* q    = (const float*)d_in[0];
    const float* k    = (const float*)d_in[1];
    const float* v    = (const float*)d_in[2];
    const int*   mask = (const int*)  d_in[3];
    const float* wq_w = (const float*)d_in[4];
    const float* wq_b = (const float*)d_in[5];
    const float* wk_w = (const float*)d_in[6];
    const float* wk_b = (const float*)d_in[7];
    const float* wv_w = (const float*)d_in[8];
    const float* wv_b = (const float*)d_in[9];
    const float* wo_w = (const float*)d_in[10];
    const float* wo_b = (const float*)d_in[11];

    float* out = (float*)d_out;
    float* att = nullptr;
    long long need = (long long)Bb*Ss*Dd + (long long)Bb*Hh*Ss*Ss;
    if ((long long)out_size >= need) att = out + (size_t)Bb*Ss*Dd;

    cudaFuncSetAttribute(attn_kernel, cudaFuncAttributeMaxDynamicSharedMemorySize,
                         ATTN_SMEM);
    cudaFuncSetAttribute(gemm_qkv, cudaFuncAttributeMaxDynamicSharedMemorySize,
                         GEMM_SMEM);
    cudaFuncSetAttribute(gemm_o, cudaFuncAttributeMaxDynamicSharedMemorySize,
                         GEMM_SMEM);

    convert_all<<<16384, 256>>>(q, k, v, wq_w, wk_w, wv_w, wo_w);

    gemm_qkv<<<dim3(Dd/128, Mm/128, 3), 256, GEMM_SMEM>>>(wq_b, wk_b, wv_b);

    attn_kernel<<<dim3(Ss/BQ, Bb*Hh), 256, ATTN_SMEM>>>(mask, att);

    gemm_o<<<dim3(Dd/128, Mm/128), 256, GEMM_SMEM>>>(wo_b, out);
}

// round 14
// speedup vs baseline: 1.5213x; 1.5213x over previous
#include <cuda_runtime.h>
#include <cuda_fp16.h>
#include <cstdint>

#define Bb 2
#define Ss 2048
#define Dd 1024
#define Hh 16
#define DKk 64
#define Mm (Bb*Ss)
#define NTILE (Ss/64)

// Scratch (allocation-free rule: __device__ globals). fp16 internal datapath.
__device__ __half g_Xh[(size_t)3*Mm*Dd];       // converted q,k,v inputs
__device__ __half g_Wh[(size_t)4*Dd*Dd];       // converted wq,wk,wv,wo
__device__ __half g_Qh[(size_t)Bb*Hh*Ss*DKk];  // holds Qh * 0.125 * log2(e)
__device__ __half g_Kh[(size_t)Bb*Hh*Ss*DKk];
__device__ __half g_Vh[(size_t)Bb*Hh*Ss*DKk];
__device__ __half g_ctx[(size_t)Bb*Ss*Dd];

// ---------------- PTX helpers ----------------
__device__ __forceinline__ uint32_t sptr(const void* p){
    return (uint32_t)__cvta_generic_to_shared(p);
}
__device__ __forceinline__ void cpa16(uint32_t s, const void* g){
    asm volatile("cp.async.ca.shared.global [%0], [%1], 16;\n" :: "r"(s), "l"(g));
}
__device__ __forceinline__ void cpa4(uint32_t s, const void* g){
    asm volatile("cp.async.ca.shared.global [%0], [%1], 4;\n" :: "r"(s), "l"(g));
}
__device__ __forceinline__ void cp_commit(){ asm volatile("cp.async.commit_group;\n"); }
template<int N> __device__ __forceinline__ void cp_wait(){
    asm volatile("cp.async.wait_group %0;\n" :: "n"(N));
}

__device__ __forceinline__ void ldsm4(uint32_t a, uint32_t* r){
    asm volatile("ldmatrix.sync.aligned.m8n8.x4.shared.b16 {%0,%1,%2,%3},[%4];\n"
        : "=r"(r[0]), "=r"(r[1]), "=r"(r[2]), "=r"(r[3]) : "r"(a));
}
__device__ __forceinline__ void ldsm4t(uint32_t a, uint32_t* r){
    asm volatile("ldmatrix.sync.aligned.m8n8.x4.trans.shared.b16 {%0,%1,%2,%3},[%4];\n"
        : "=r"(r[0]), "=r"(r[1]), "=r"(r[2]), "=r"(r[3]) : "r"(a));
}

__device__ __forceinline__ void mma16(float* c,
    uint32_t a0, uint32_t a1, uint32_t a2, uint32_t a3, uint32_t b0, uint32_t b1)
{
    asm volatile(
      "mma.sync.aligned.m16n8k16.row.col.f32.f16.f16.f32 "
      "{%0,%1,%2,%3},{%4,%5,%6,%7},{%8,%9},{%0,%1,%2,%3};\n"
      : "+f"(c[0]), "+f"(c[1]), "+f"(c[2]), "+f"(c[3])
      : "r"(a0), "r"(a1), "r"(a2), "r"(a3), "r"(b0), "r"(b1));
}

__device__ __forceinline__ void sth2(__half* p, float lo, float hi){
    *(__half2*)p = __floats2half2_rn(lo, hi);
}
__device__ __forceinline__ uint32_t packh2(float lo, float hi){
    __half2 h = __floats2half2_rn(lo, hi);
    return *(uint32_t*)&h;
}
__device__ __forceinline__ float ex2(float x){
    float y; asm("ex2.approx.ftz.f32 %0, %1;" : "=f"(y) : "f"(x)); return y;
}

// head-layout index: m=(b*S+s), n=(h*64+dk) -> [b][h][s][dk]
__device__ __forceinline__ size_t hidx(int m, int n){
    int b = m >> 11;
    int s = m & 2047;
    int h = n >> 6;
    int dk = n & 63;
    return (((size_t)b*Hh + h)*Ss + s)*DKk + dk;
}

// ---------------------------------------------------------------------------
// Convert q,k,v (3 x 2^22 elems) and 4 weights (4 x 2^20) fp32 -> fp16.
// One thread per float4 (2^22 total).
// ---------------------------------------------------------------------------
__global__ void __launch_bounds__(256)
convert_all(const float* __restrict__ q, const float* __restrict__ k,
            const float* __restrict__ v,
            const float* __restrict__ wq, const float* __restrict__ wk,
            const float* __restrict__ wv, const float* __restrict__ wo)
{
    size_t t = (size_t)blockIdx.x*256 + threadIdx.x;
    const float* src; __half* dst; size_t off;
    if (t < ((size_t)3<<20)) {
        int which = (int)(t >> 20);
        off = t & 0xFFFFFu;
        src = (which == 0) ? q : (which == 1) ? k : v;
        dst = g_Xh + ((size_t)which << 22);
    } else {
        size_t t2 = t - ((size_t)3<<20);
        int which = (int)(t2 >> 18);
        off = t2 & 0x3FFFFu;
        src = (which == 0) ? wq : (which == 1) ? wk : (which == 2) ? wv : wo;
        dst = g_Wh + ((size_t)which << 20);
    }
    float4 vv = ((const float4*)src)[off];
    __half2 h0 = __floats2half2_rn(vv.x, vv.y);
    __half2 h1 = __floats2half2_rn(vv.z, vv.w);
    uint2 u; u.x = *(uint32_t*)&h0; u.y = *(uint32_t*)&h1;
    ((uint2*)dst)[off] = u;
}

// ---------------------------------------------------------------------------
// All-half projection GEMM: C[4096,1024] = X @ W^T + bias, cp.async 2-stage.
// Block 128x128, BK=32, 8 warps (2m x 4n), warp 64x32.
// ---------------------------------------------------------------------------
#define GST 40   // smem row stride in halves (80B, 16B-aligned, LDSM conflict-free)

template<bool HEADOUT>
__device__ __forceinline__ void gemm_body(const __half* __restrict__ X,
                                          const __half* __restrict__ W,
                                          const float* __restrict__ bias,
                                          void* __restrict__ opv,
                                          float oscale)
{
    __shared__ __half As[2][128*GST];
    __shared__ __half Bs[2][128*GST];

    const int tid = threadIdx.x;
    const int lane = tid & 31, w = tid >> 5;
    const int wm = w >> 2, wn = w & 3;
    const int g = lane >> 2, tg = lane & 3;
    const int by = blockIdx.y, bx = blockIdx.x;

    const int a_off_r = (lane & 7) + ((lane >> 3) & 1) * 8;
    const int a_off_c = (lane >> 4) << 3;
    const int b_off_r = (lane & 7) + ((lane >> 4) << 3);
    const int b_off_c = ((lane >> 3) & 1) << 3;

    const __half* xblk = X + (size_t)(by*128) * Dd;
    const __half* wblk = W + (size_t)(bx*128) * Dd;

    const int ldr = tid >> 2;            // 0..63
    const int ldc = (tid & 3) * 8;       // 0,8,16,24

    float acc[4][4][4];
    #pragma unroll
    for (int mt = 0; mt < 4; mt++)
        #pragma unroll
        for (int nt = 0; nt < 4; nt++)
            #pragma unroll
            for (int j = 0; j < 4; j++) acc[mt][nt][j] = 0.f;

    // tile loader: stage st <- k-tile kt
    auto load_tile = [&](int kt, int st){
        const __half* xs = xblk + kt*32;
        const __half* ws = wblk + kt*32;
        #pragma unroll
        for (int i = 0; i < 2; i++) {
            int r = ldr + 64*i;
            cpa16(sptr(&As[st][r*GST + ldc]), xs + (size_t)r*Dd + ldc);
            cpa16(sptr(&Bs[st][r*GST + ldc]), ws + (size_t)r*Dd + ldc);
        }
    };

    load_tile(0, 0); cp_commit();

    for (int kt = 0; kt < Dd/32; kt++) {
        int cur = kt & 1;
        if (kt + 1 < Dd/32) {
            load_tile(kt + 1, 1 - cur); cp_commit();
            cp_wait<1>();
        } else {
            cp_wait<0>();
        }
        __syncthreads();

        #pragma unroll
        for (int ks = 0; ks < 32; ks += 16) {
            uint32_t aF[4][4], bF[2][4];
            #pragma unroll
            for (int mt = 0; mt < 4; mt++)
                ldsm4(sptr(&As[cur][(wm*64 + mt*16 + a_off_r)*GST + ks + a_off_c]), aF[mt]);
            #pragma unroll
            for (int ntp = 0; ntp < 2; ntp++)
                ldsm4(sptr(&Bs[cur][(wn*32 + ntp*16 + b_off_r)*GST + ks + b_off_c]), bF[ntp]);
            #pragma unroll
            for (int mt = 0; mt < 4; mt++)
                #pragma unroll
                for (int nt = 0; nt < 4; nt++)
                    mma16(acc[mt][nt], aF[mt][0], aF[mt][1], aF[mt][2], aF[mt][3],
                          bF[nt>>1][(nt&1)*2], bF[nt>>1][(nt&1)*2 + 1]);
        }
        __syncthreads();
    }

    #pragma unroll
    for (int mt = 0; mt < 4; mt++) {
        int m0 = by*128 + wm*64 + mt*16 + g;
        #pragma unroll
        for (int nt = 0; nt < 4; nt++) {
            int n0 = bx*128 + wn*32 + nt*8 + tg*2;
            float bv0 = bias[n0], bv1 = bias[n0 + 1];
            if (HEADOUT) {
                __half* op = (__half*)opv;
                sth2(&op[hidx(m0,     n0)], (acc[mt][nt][0] + bv0) * oscale,
                                            (acc[mt][nt][1] + bv1) * oscale);
                sth2(&op[hidx(m0 + 8, n0)], (acc[mt][nt][2] + bv0) * oscale,
                                            (acc[mt][nt][3] + bv1) * oscale);
            } else {
                float* op = (float*)opv;
                *(float2*)&op[(size_t)m0*Dd + n0] =
                    make_float2(acc[mt][nt][0] + bv0, acc[mt][nt][1] + bv1);
                *(float2*)&op[(size_t)(m0+8)*Dd + n0] =
                    make_float2(acc[mt][nt][2] + bv0, acc[mt][nt][3] + bv1);
            }
        }
    }
}

__global__ void __launch_bounds__(256, 2)
gemm_qkv(const float* __restrict__ bq, const float* __restrict__ bk,
         const float* __restrict__ bv)
{
    int mode = blockIdx.z;
    const __half* X = g_Xh + ((size_t)mode << 22);
    const __half* W = g_Wh + ((size_t)mode << 20);
    const float* B = (mode == 0) ? bq : (mode == 1) ? bk : bv;
    __half* op = (mode == 0) ? g_Qh : (mode == 1) ? g_Kh : g_Vh;
    // fold 1/sqrt(Dk) * log2(e) into Q so softmax uses raw ex2
    float sc = (mode == 0) ? 0.125f * 1.4426950408889634f : 1.0f;
    gemm_body<true>(X, W, B, op, sc);
}

__global__ void __launch_bounds__(256, 2)
gemm_o(const float* __restrict__ bias, float* __restrict__ outp)
{
    gemm_body<false>(g_ctx, g_Wh + ((size_t)3 << 20), bias, outp, 1.0f);
}

// ---------------------------------------------------------------------------
// Attention. q-tile = 128 rows, 8 warps, each warp = 16 q-rows x FULL 64 cols.
// Q fragments hoisted to registers. Pass 1: sumexp only (scores are base-2).
// Pass 2: recompute scores, write normalized fp32 attention, AV mma with
// P kept entirely in registers (score C-frags == AV A-frags layout).
// ---------------------------------------------------------------------------
#define HST 72
#define BQ 128

__global__ void __launch_bounds__(256, 2)
attn_kernel(const int* __restrict__ mask, float* __restrict__ att)
{
    extern __shared__ __half smh[];
    __half* Qs  = smh;                  // 128*HST
    __half* Kb0 = Qs  + BQ*HST;         // 64*HST
    __half* Kb1 = Kb0 + 64*HST;
    __half* Vb0 = Kb1 + 64*HST;
    __half* Vb1 = Vb0 + 64*HST;
    int*   maskv = (int*)(Vb1 + 64*HST);   // 2*64

    const int tid = threadIdx.x;
    const int lane = tid & 31, w = tid >> 5;     // warp owns rows w*16..w*16+15
    const int g = lane >> 2, tg = lane & 3;
    const int qb = blockIdx.x, bh = blockIdx.y;
    const int b = bh >> 4, hd = bh & 15;

    const int a_off_r = (lane & 7) + ((lane >> 3) & 1) * 8;
    const int a_off_c = (lane >> 4) << 3;
    const int b_off_r = (lane & 7) + ((lane >> 4) << 3);
    const int b_off_c = ((lane >> 3) & 1) << 3;
    const int v_off_r = (lane & 7) + (((lane >> 3) & 1) << 3);
    const int v_off_c = (lane >> 4) << 3;

    const __half* Qg = g_Qh + ((size_t)bh*Ss + qb*BQ) * DKk;
    const __half* Kg = g_Kh + (size_t)bh*Ss*DKk;
    const __half* Vg = g_Vh + (size_t)bh*Ss*DKk;
    const int*    mg = mask + b*Ss;

    // prologue: Q tile + K tile 0 + mask 0
    #pragma unroll
    for (int i = 0; i < 4; i++) {
        int id = tid + 256*i, r = id >> 3, c = (id & 7)*8;
        cpa16(sptr(&Qs[r*HST + c]), Qg + r*64 + c);
    }
    #pragma unroll
    for (int i = 0; i < 2; i++) {
        int id = tid + 256*i, r = id >> 3, c = (id & 7)*8;
        cpa16(sptr(&Kb0[r*HST + c]), Kg + r*64 + c);
    }
    if (tid < 64) cpa4(sptr(&maskv[tid]), mg + tid);
    cp_commit();
    cp_wait<0>();
    __syncthreads();

    // Q fragments once (16 rows x 64 cols per warp)
    uint32_t qF[4][4];
    #pragma unroll
    for (int ksi = 0; ksi < 4; ksi++)
        ldsm4(sptr(&Qs[(w*16 + a_off_r)*HST + ksi*16 + a_off_c]), qF[ksi]);

    // ----------------- Pass 1: row sumexp -----------------
    float lp[2] = {0.f, 0.f};

    for (int kt = 0; kt < NTILE; kt++) {
        int cur = kt & 1;
        __half* Ksb = cur ? Kb1 : Kb0;
        const int* mk = maskv + cur*64;

        if (kt + 1 < NTILE) {
            __half* Kn = cur ? Kb0 : Kb1;
            const __half* src = Kg + (size_t)(kt+1)*64*64;
            #pragma unroll
            for (int i = 0; i < 2; i++) {
                int id = tid + 256*i, r = id >> 3, c = (id & 7)*8;
                cpa16(sptr(&Kn[r*HST + c]), src + r*64 + c);
            }
            if (tid < 64) cpa4(sptr(&maskv[(1-cur)*64 + tid]), mg + (kt+1)*64 + tid);
            cp_commit();
            cp_wait<1>();
        } else {
            cp_wait<0>();
        }
        __syncthreads();

        float sa[8][4];
        #pragma unroll
        for (int nt = 0; nt < 8; nt++)
            #pragma unroll
            for (int j = 0; j < 4; j++) sa[nt][j] = 0.f;

        #pragma unroll
        for (int ksi = 0; ksi < 4; ksi++) {
            uint32_t bF[4][4];
            #pragma unroll
            for (int np = 0; np < 4; np++)
                ldsm4(sptr(&Ksb[(np*16 + b_off_r)*HST + ksi*16 + b_off_c]), bF[np]);
            #pragma unroll
            for (int nt = 0; nt < 8; nt++)
                mma16(sa[nt], qF[ksi][0], qF[ksi][1], qF[ksi][2], qF[ksi][3],
                      bF[nt>>1][(nt&1)*2], bF[nt>>1][(nt&1)*2 + 1]);
        }

        #pragma unroll
        for (int nt = 0; nt < 8; nt++) {
            int c0 = nt*8 + 2*tg;
            int m0 = mk[c0], m1 = mk[c0 + 1];
            float s0 = m0 ? sa[nt][0] : -1e9f;
            float s1 = m1 ? sa[nt][1] : -1e9f;
            float s2 = m0 ? sa[nt][2] : -1e9f;
            float s3 = m1 ? sa[nt][3] : -1e9f;
            lp[0] += ex2(s0) + ex2(s1);
            lp[1] += ex2(s2) + ex2(s3);
        }
        __syncthreads();
    }

    // reduce over tg lanes only (warp owns full rows)
    float fil[2];
    #pragma unroll
    for (int e = 0; e < 2; e++) {
        float l = lp[e];
        l += __shfl_xor_sync(0xffffffffu, l, 1);
        l += __shfl_xor_sync(0xffffffffu, l, 2);
        fil[e] = 1.0f / l;
    }

    // issue pass-2 tile 0 (K+V+mask)
    #pragma unroll
    for (int i = 0; i < 2; i++) {
        int id = tid + 256*i, r = id >> 3, c = (id & 7)*8;
        cpa16(sptr(&Kb0[r*HST + c]), Kg + r*64 + c);
        cpa16(sptr(&Vb0[r*HST + c]), Vg + r*64 + c);
    }
    if (tid < 64) cpa4(sptr(&maskv[tid]), mg + tid);
    cp_commit();

    // ----------------- Pass 2: attention write + A@V -----------------
    float av[8][4];
    #pragma unroll
    for (int nt = 0; nt < 8; nt++)
        #pragma unroll
        for (int j = 0; j < 4; j++) av[nt][j] = 0.f;

    const int row0 = qb*BQ + w*16 + g;
    float* attr0 = att ? att + ((size_t)bh*Ss + row0)*Ss : nullptr;
    float* attr1 = att ? attr0 + 8*Ss : nullptr;

    for (int kt = 0; kt < NTILE; kt++) {
        int cur = kt & 1;
        __half* Ksb = cur ? Kb1 : Kb0;
        __half* Vsb = cur ? Vb1 : Vb0;
        const int* mk = maskv + cur*64;

        if (kt + 1 < NTILE) {
            __half* Kn = cur ? Kb0 : Kb1;
            __half* Vn = cur ? Vb0 : Vb1;
            const __half* ksrc = Kg + (size_t)(kt+1)*64*64;
            const __half* vsrc = Vg + (size_t)(kt+1)*64*64;
            #pragma unroll
            for (int i = 0; i < 2; i++) {
                int id = tid + 256*i, r = id >> 3, c = (id & 7)*8;
                cpa16(sptr(&Kn[r*HST + c]), ksrc + r*64 + c);
                cpa16(sptr(&Vn[r*HST + c]), vsrc + r*64 + c);
            }
            if (tid < 64) cpa4(sptr(&maskv[(1-cur)*64 + tid]), mg + (kt+1)*64 + tid);
            cp_commit();
            cp_wait<1>();
        } else {
            cp_wait<0>();
        }
        __syncthreads();

        float sa[8][4];
        #pragma unroll
        for (int nt = 0; nt < 8; nt++)
            #pragma unroll
            for (int j = 0; j < 4; j++) sa[nt][j] = 0.f;

        #pragma unroll
        for (int ksi = 0; ksi < 4; ksi++) {
            uint32_t bF[4][4];
            #pragma unroll
            for (int np = 0; np < 4; np++)
                ldsm4(sptr(&Ksb[(np*16 + b_off_r)*HST + ksi*16 + b_off_c]), bF[np]);
            #pragma unroll
            for (int nt = 0; nt < 8; nt++)
                mma16(sa[nt], qF[ksi][0], qF[ksi][1], qF[ksi][2], qF[ksi][3],
                      bF[nt>>1][(nt&1)*2], bF[nt>>1][(nt&1)*2 + 1]);
        }

        // softmax values: overwrite sa with p, write fp32 attention
        #pragma unroll
        for (int nt = 0; nt < 8; nt++) {
            int c0 = nt*8 + 2*tg;
            int m0 = mk[c0], m1 = mk[c0 + 1];
            float p0 = m0 ? ex2(sa[nt][0]) * fil[0] : 0.f;
            float p1 = m1 ? ex2(sa[nt][1]) * fil[0] : 0.f;
            float p2 = m0 ? ex2(sa[nt][2]) * fil[1] : 0.f;
            float p3 = m1 ? ex2(sa[nt][3]) * fil[1] : 0.f;
            if (att) {
                *(float2*)&attr0[kt*64 + c0] = make_float2(p0, p1);
                *(float2*)&attr1[kt*64 + c0] = make_float2(p2, p3);
            }
            sa[nt][0] = p0; sa[nt][1] = p1; sa[nt][2] = p2; sa[nt][3] = p3;
        }

        // AV: A-frags straight from registers, B-frags via ldmatrix.trans on V
        #pragma unroll
        for (int ksi = 0; ksi < 4; ksi++) {
            uint32_t ap0 = packh2(sa[2*ksi][0],   sa[2*ksi][1]);
            uint32_t ap1 = packh2(sa[2*ksi][2],   sa[2*ksi][3]);
            uint32_t ap2 = packh2(sa[2*ksi+1][0], sa[2*ksi+1][1]);
            uint32_t ap3 = packh2(sa[2*ksi+1][2], sa[2*ksi+1][3]);
            uint32_t bV[4][4];
            #pragma unroll
            for (int np = 0; np < 4; np++)
                ldsm4t(sptr(&Vsb[(ksi*16 + v_off_r)*HST + np*16 + v_off_c]), bV[np]);
            #pragma unroll
            for (int nt = 0; nt < 8; nt++)
                mma16(av[nt], ap0, ap1, ap2, ap3,
                      bV[nt>>1][(nt&1)*2], bV[nt>>1][(nt&1)*2 + 1]);
        }
        __syncthreads();
    }

    // ctx epilogue: ctx[b][s][h*64+dk] as half
    #pragma unroll
    for (int nt = 0; nt < 8; nt++) {
        int dk = nt*8 + 2*tg;
        size_t i0 = ((size_t)b*Ss + row0)*Dd + hd*DKk + dk;
        sth2(&g_ctx[i0],          av[nt][0], av[nt][1]);
        sth2(&g_ctx[i0 + 8*Dd],   av[nt][2], av[nt][3]);
    }
}

// ---------------------------------------------------------------------------

extern "C" void kernel_launch(void* const* d_in, const int* in_sizes, int n_in,
                              void* d_out, int out_size)
{
    const float* q    = (const float*)d_in[0];
    const float* k    = (const float*)d_in[1];
    const float* v    = (const float*)d_in[2];
    const int*   mask = (const int*)  d_in[3];
    const float* wq_w = (const float*)d_in[4];
    const float* wq_b = (const float*)d_in[5];
    const float* wk_w = (const float*)d_in[6];
    const float* wk_b = (const float*)d_in[7];
    const float* wv_w = (const float*)d_in[8];
    const float* wv_b = (const float*)d_in[9];
    const float* wo_w = (const float*)d_in[10];
    const float* wo_b = (const float*)d_in[11];

    float* out = (float*)d_out;
    float* att = nullptr;
    long long need = (long long)Bb*Ss*Dd + (long long)Bb*Hh*Ss*Ss;
    if ((long long)out_size >= need) att = out + (size_t)Bb*Ss*Dd;

    const int attn_smem = (BQ*HST + 4*64*HST) * 2 + 2*64*4;
    cudaFuncSetAttribute(attn_kernel, cudaFuncAttributeMaxDynamicSharedMemorySize,
                         attn_smem);

    convert_all<<<16384, 256>>>(q, k, v, wq_w, wk_w, wv_w, wo_w);

    gemm_qkv<<<dim3(Dd/128, Mm/128, 3), 256>>>(wq_b, wk_b, wv_b);

    attn_kernel<<<dim3(Ss/BQ, Bb*Hh), 256, attn_smem>>>(mask, att);

    gemm_o<<<dim3(Dd/128, Mm/128), 256>>>(wo_b, out);
}